// round 3
// baseline (speedup 1.0000x reference)
#include <cuda_runtime.h>
#include <cuda_bf16.h>

// SoftVectorQuantizer on GB300 — Round 1 fp32 baseline.
//
// Math: softmax(-dists) row-wise; ||z||^2 cancels, so
//   l_k    = 2*z.e_k - ||e_k||^2          (logits, tiny spread -> no max sub)
//   w_k    = exp(l_k)
//   z_soft = (sum_k w_k e_k) / (sum_k w_k)
//   loss   = mean((z_soft - z)^2)
//
// Structure: per block: 64 z-rows, loop over 16 K-chunks of 64 codes:
//   phase1 GEMM 64x64x256 (logits), exp -> smem weights + denom partials,
//   phase2 GEMM 64x256x64 accumulating z_soft in registers.
// Deterministic: no float atomics anywhere (fixed-order partial sums).

#define D        256
#define KTOT     1024
#define TILE_M   64
#define KC       64
#define ZSTRIDE  65   // float4 chunks per padded smem row (260 floats)
#define WSTRIDE  68   // floats per sW row

__device__ float g_ce[KTOT];
__device__ float g_block_loss[4096];

__global__ void ce_kernel(const float* __restrict__ cb) {
    int k = blockIdx.x * blockDim.x + threadIdx.x;
    if (k < KTOT) {
        const float4* r = reinterpret_cast<const float4*>(cb + (size_t)k * D);
        float s = 0.f;
        #pragma unroll 8
        for (int i = 0; i < D / 4; i++) {
            float4 v = r[i];
            s += v.x * v.x + v.y * v.y + v.z * v.z + v.w * v.w;
        }
        g_ce[k] = s;
    }
}

extern __shared__ float smem[];

__global__ void __launch_bounds__(256, 1) svq_main(
    const float* __restrict__ z, const float* __restrict__ cb,
    float* __restrict__ out)
{
    // smem layout (floats)
    float* sZ    = smem;                      // 64 * 260
    float* sE    = sZ + TILE_M * 260;         // 64 * 260
    float* sW    = sE + KC * 260;             // 64 * 68
    float* sDenP = sW + TILE_M * WSTRIDE;     // 64 * 16
    float* sDen  = sDenP + TILE_M * 16;       // 64
    float* sRed  = sDen + TILE_M;             // 8

    const int tid = threadIdx.x;
    const int mt  = tid & 15;   // row group: rows mt + 16*i
    const int kt  = tid >> 4;   // phase1: code group; phase2: dim group

    const int rowBase = blockIdx.x * TILE_M;

    // zero denom partials
    for (int i = tid; i < TILE_M * 16; i += 256) sDenP[i] = 0.f;

    // load z tile [64][256] -> padded smem rows
    {
        const float4* g  = reinterpret_cast<const float4*>(z + (size_t)rowBase * D);
        float4*       s4 = reinterpret_cast<float4*>(sZ);
        for (int t = tid; t < TILE_M * 64; t += 256) {
            int r = t >> 6, c = t & 63;
            s4[r * ZSTRIDE + c] = g[r * 64 + c];
        }
    }

    float4 acc2[4][4];
    #pragma unroll
    for (int i = 0; i < 4; i++)
        #pragma unroll
        for (int j = 0; j < 4; j++) acc2[i][j] = make_float4(0.f, 0.f, 0.f, 0.f);

    const float4* sZ4 = reinterpret_cast<const float4*>(sZ);
    const float4* sE4 = reinterpret_cast<const float4*>(sE);

    for (int ch = 0; ch < KTOT / KC; ch++) {
        __syncthreads();  // prior phase2 done reading sE/sW; also covers init/z-load on ch=0

        // load codebook chunk [64][256] -> padded smem rows
        {
            const float4* g  = reinterpret_cast<const float4*>(cb + (size_t)ch * KC * D);
            float4*       s4 = reinterpret_cast<float4*>(sE);
            for (int t = tid; t < KC * 64; t += 256) {
                int r = t >> 6, c = t & 63;
                s4[r * ZSTRIDE + c] = g[r * 64 + c];
            }
        }
        __syncthreads();

        // ---- phase 1: logits tile 64x64 (4x4 register tile per thread) ----
        float a1[4][4];
        #pragma unroll
        for (int i = 0; i < 4; i++)
            #pragma unroll
            for (int j = 0; j < 4; j++) a1[i][j] = 0.f;

        #pragma unroll 2
        for (int d4 = 0; d4 < D / 4; d4++) {
            float4 av[4], bv[4];
            #pragma unroll
            for (int i = 0; i < 4; i++) av[i] = sZ4[(mt + 16 * i) * ZSTRIDE + d4];
            #pragma unroll
            for (int j = 0; j < 4; j++) bv[j] = sE4[(kt + 16 * j) * ZSTRIDE + d4];
            #pragma unroll
            for (int i = 0; i < 4; i++)
                #pragma unroll
                for (int j = 0; j < 4; j++) {
                    a1[i][j] += av[i].x * bv[j].x;
                    a1[i][j] += av[i].y * bv[j].y;
                    a1[i][j] += av[i].z * bv[j].z;
                    a1[i][j] += av[i].w * bv[j].w;
                }
        }

        // exp, stash weights, accumulate per-(row,kt) denominator partials
        #pragma unroll
        for (int i = 0; i < 4; i++) {
            float rs = 0.f;
            #pragma unroll
            for (int j = 0; j < 4; j++) {
                int   kk = kt + 16 * j;
                float l  = 2.f * a1[i][j] - g_ce[ch * KC + kk];
                float w  = __expf(l);
                sW[(mt + 16 * i) * WSTRIDE + kk] = w;
                rs += w;
            }
            sDenP[(mt + 16 * i) * 16 + kt] += rs;  // single owner per slot: deterministic
        }
        __syncthreads();

        // ---- phase 2: acc2 += W * E  (rows mt+16i, dims 16*kt..16*kt+15) ----
        #pragma unroll 2
        for (int k = 0; k < KC; k++) {
            float wv[4];
            #pragma unroll
            for (int i = 0; i < 4; i++) wv[i] = sW[(mt + 16 * i) * WSTRIDE + k];
            float4 ev[4];
            #pragma unroll
            for (int j = 0; j < 4; j++) ev[j] = sE4[k * ZSTRIDE + kt * 4 + j];
            #pragma unroll
            for (int i = 0; i < 4; i++)
                #pragma unroll
                for (int j = 0; j < 4; j++) {
                    acc2[i][j].x += wv[i] * ev[j].x;
                    acc2[i][j].y += wv[i] * ev[j].y;
                    acc2[i][j].z += wv[i] * ev[j].z;
                    acc2[i][j].w += wv[i] * ev[j].w;
                }
        }
    }
    __syncthreads();

    // finalize denominators in fixed order
    if (tid < TILE_M) {
        float s = 0.f;
        #pragma unroll
        for (int q = 0; q < 16; q++) s += sDenP[tid * 16 + q];
        sDen[tid] = s;
    }
    __syncthreads();

    // normalize, write z_soft, accumulate loss partial
    float  lsum = 0.f;
    float4* out4 = reinterpret_cast<float4*>(out);
    #pragma unroll
    for (int i = 0; i < 4; i++) {
        int    row = mt + 16 * i;
        float  inv = 1.f / sDen[row];
        size_t ob  = (size_t)(rowBase + row) * (D / 4);
        #pragma unroll
        for (int j = 0; j < 4; j++) {
            float4 v = acc2[i][j];
            v.x *= inv; v.y *= inv; v.z *= inv; v.w *= inv;
            float4 zv = sZ4[row * ZSTRIDE + kt * 4 + j];
            float dx = v.x - zv.x, dy = v.y - zv.y, dz = v.z - zv.z, dw = v.w - zv.w;
            lsum += dx * dx + dy * dy + dz * dz + dw * dw;
            out4[ob + kt * 4 + j] = v;
        }
    }

    // deterministic block reduction of loss
    #pragma unroll
    for (int off = 16; off > 0; off >>= 1)
        lsum += __shfl_down_sync(0xffffffffu, lsum, off);
    if ((tid & 31) == 0) sRed[tid >> 5] = lsum;
    __syncthreads();
    if (tid == 0) {
        float s = 0.f;
        #pragma unroll
        for (int w = 0; w < 8; w++) s += sRed[w];
        g_block_loss[blockIdx.x] = s;
    }
}

__global__ void loss_finalize(float* __restrict__ out, int nblocks,
                              float inv_nd, int loss_idx) {
    __shared__ float sh[256];
    int tid = threadIdx.x;
    float s = 0.f;
    for (int i = tid; i < nblocks; i += 256) s += g_block_loss[i];  // fixed order
    sh[tid] = s;
    __syncthreads();
    for (int off = 128; off > 0; off >>= 1) {
        if (tid < off) sh[tid] += sh[tid + off];
        __syncthreads();
    }
    if (tid == 0) out[loss_idx] = sh[0] * inv_nd;
}

extern "C" void kernel_launch(void* const* d_in, const int* in_sizes, int n_in,
                              void* d_out, int out_size) {
    const float* z  = (const float*)d_in[0];
    const float* cb = (const float*)d_in[1];
    int sz0 = in_sizes[0], sz1 = in_sizes[1];
    if (sz0 < sz1) {  // robustness: z is the big tensor
        const float* t = z; z = cb; cb = t;
        int ts = sz0; sz0 = sz1; sz1 = ts;
    }
    float* out = (float*)d_out;

    int nrows   = sz0 / D;          // 131072
    int nblocks = nrows / TILE_M;   // 2048

    const int SMEM_BYTES =
        (TILE_M * 260 + KC * 260 + TILE_M * WSTRIDE + TILE_M * 16 + TILE_M + 8)
        * (int)sizeof(float);       // ~154.9 KB

    cudaFuncSetAttribute(svq_main, cudaFuncAttributeMaxDynamicSharedMemorySize,
                         SMEM_BYTES);

    ce_kernel<<<(KTOT + 127) / 128, 128>>>(cb);
    svq_main<<<nblocks, 256, SMEM_BYTES>>>(z, cb, out);

    float inv_nd = 1.0f / ((float)nrows * (float)D);
    loss_finalize<<<1, 256>>>(out, nblocks, inv_nd, out_size - 1);
}